// round 1
// baseline (speedup 1.0000x reference)
#include <cuda_runtime.h>

#define BATCH 32768
#define HDIM  1024
#define NFAM  10

// ---------------- scratch (no allocations allowed) ----------------
__device__ int   g_nearest[BATCH];
__device__ float g_protoW1[NFAM * HDIM];
__device__ float g_hidden[(size_t)BATCH * HDIM];   // 128 MiB scratch

// ---------------- kernel 1: nearest prototype ----------------
// argmin_j (f2 + p2 - 2 f.p) == argmin_j (p2 - 2 f.p) == argmin_j sum_h p*(p - 2f)
__global__ __launch_bounds__(256) void argmin_kernel(const float* __restrict__ feat,
                                                     const float* __restrict__ protos) {
    __shared__ float sp[NFAM * HDIM];   // 40 KB
    for (int i = threadIdx.x; i < NFAM * HDIM; i += 256)
        sp[i] = protos[i];
    __syncthreads();

    const int warp = threadIdx.x >> 5;
    const int lane = threadIdx.x & 31;
    const int row  = blockIdx.x * 8 + warp;
    const float* f = feat + (size_t)row * HDIM;

    float acc[NFAM];
#pragma unroll
    for (int j = 0; j < NFAM; ++j) acc[j] = 0.f;

    for (int h = lane; h < HDIM; h += 32) {
        const float fv = f[h];
#pragma unroll
        for (int j = 0; j < NFAM; ++j) {
            const float p = sp[j * HDIM + h];
            acc[j] = fmaf(p, p - 2.f * fv, acc[j]);
        }
    }
#pragma unroll
    for (int j = 0; j < NFAM; ++j) {
#pragma unroll
        for (int o = 16; o > 0; o >>= 1)
            acc[j] += __shfl_xor_sync(0xffffffffu, acc[j], o);
    }
    if (lane == 0) {
        float best = acc[0];
        int   bi   = 0;
#pragma unroll
        for (int j = 1; j < NFAM; ++j)
            if (acc[j] < best) { best = acc[j]; bi = j; }
        g_nearest[row] = bi;
    }
}

// ---------------- kernel 2: protoW1[j] = b1 + protos[j] @ W1[H:2H, :] ----------------
__global__ __launch_bounds__(256) void protow1_kernel(const float* __restrict__ protos,
                                                      const float* __restrict__ W1,
                                                      const float* __restrict__ b1) {
    const int n = blockIdx.x * 256 + threadIdx.x;   // 0..1023
    const int j = blockIdx.y;                       // 0..9
    const float* p = protos + j * HDIM;
    const float* w = W1 + (size_t)HDIM * HDIM + n;  // bottom half of W1
    float acc = b1[n];
#pragma unroll 8
    for (int h = 0; h < HDIM; ++h)
        acc = fmaf(p[h], w[(size_t)h * HDIM], acc);
    g_protoW1[j * HDIM + n] = acc;
}

// ---------------- GEMM core: C[128x128 tile] = A[M,1024] @ B[1024,1024] (+epilogue) ---
// BM=BN=128, BK=8, 256 threads, 8x8 per-thread microtile, double-buffered smem.
template <bool FUSE1>
__device__ __forceinline__ void sgemm_core(const float* __restrict__ A,
                                           const float* __restrict__ B,
                                           float* __restrict__ C,
                                           const float* __restrict__ addvec) {
    const int K = HDIM, N = HDIM;
    __shared__ float As[2][8][128];
    __shared__ float Bs[2][8][128];

    const int tid = threadIdx.x;
    const int bm  = blockIdx.y * 128;
    const int bn  = blockIdx.x * 128;

    const int tx      = tid & 15;   // 0..15
    const int ty      = tid >> 4;   // 0..15
    const int rowBase = ty * 8;
    const int colBase = tx * 8;

    // global->smem staging indices
    const int aRow = tid >> 1;          // 0..127
    const int aCol = (tid & 1) * 4;     // 0 or 4
    const int bRow = tid >> 5;          // 0..7
    const int bCol = (tid & 31) * 4;    // 0..124

    const float* Aptr = A + (size_t)(bm + aRow) * K + aCol;
    const float* Bptr = B + (size_t)bRow * N + bn + bCol;

    float4 aReg = *reinterpret_cast<const float4*>(Aptr);
    float4 bReg = *reinterpret_cast<const float4*>(Bptr);

    int buf = 0;
    As[buf][aCol + 0][aRow] = aReg.x;
    As[buf][aCol + 1][aRow] = aReg.y;
    As[buf][aCol + 2][aRow] = aReg.z;
    As[buf][aCol + 3][aRow] = aReg.w;
    *reinterpret_cast<float4*>(&Bs[buf][bRow][bCol]) = bReg;
    __syncthreads();

    float acc[8][8];
#pragma unroll
    for (int i = 0; i < 8; ++i)
#pragma unroll
        for (int j = 0; j < 8; ++j) acc[i][j] = 0.f;

    const int KT = K / 8;   // 128
    for (int kt = 0; kt < KT; ++kt) {
        if (kt + 1 < KT) {
            aReg = *reinterpret_cast<const float4*>(Aptr + (kt + 1) * 8);
            bReg = *reinterpret_cast<const float4*>(Bptr + (size_t)(kt + 1) * 8 * N);
        }
#pragma unroll
        for (int k = 0; k < 8; ++k) {
            float af[8], bf[8];
            *reinterpret_cast<float4*>(af)     = *reinterpret_cast<const float4*>(&As[buf][k][rowBase]);
            *reinterpret_cast<float4*>(af + 4) = *reinterpret_cast<const float4*>(&As[buf][k][rowBase + 4]);
            *reinterpret_cast<float4*>(bf)     = *reinterpret_cast<const float4*>(&Bs[buf][k][colBase]);
            *reinterpret_cast<float4*>(bf + 4) = *reinterpret_cast<const float4*>(&Bs[buf][k][colBase + 4]);
#pragma unroll
            for (int i = 0; i < 8; ++i)
#pragma unroll
                for (int j = 0; j < 8; ++j)
                    acc[i][j] = fmaf(af[i], bf[j], acc[i][j]);
        }
        if (kt + 1 < KT) {
            const int nb = buf ^ 1;
            As[nb][aCol + 0][aRow] = aReg.x;
            As[nb][aCol + 1][aRow] = aReg.y;
            As[nb][aCol + 2][aRow] = aReg.z;
            As[nb][aCol + 3][aRow] = aReg.w;
            *reinterpret_cast<float4*>(&Bs[nb][bRow][bCol]) = bReg;
            __syncthreads();
            buf = nb;
        }
    }

    // epilogue
#pragma unroll
    for (int i = 0; i < 8; ++i) {
        const int row = bm + rowBase + i;
        const float* av;
        if (FUSE1) {
            const int ix = g_nearest[row];
            av = addvec + (size_t)ix * HDIM + bn + colBase;
        } else {
            av = addvec + bn + colBase;
        }
        float4 a0 = *reinterpret_cast<const float4*>(av);
        float4 a1 = *reinterpret_cast<const float4*>(av + 4);
        float4 v0, v1;
        v0.x = acc[i][0] + a0.x; v0.y = acc[i][1] + a0.y;
        v0.z = acc[i][2] + a0.z; v0.w = acc[i][3] + a0.w;
        v1.x = acc[i][4] + a1.x; v1.y = acc[i][5] + a1.y;
        v1.z = acc[i][6] + a1.z; v1.w = acc[i][7] + a1.w;
        if (FUSE1) {
            v0.x = fmaxf(v0.x, 0.f); v0.y = fmaxf(v0.y, 0.f);
            v0.z = fmaxf(v0.z, 0.f); v0.w = fmaxf(v0.w, 0.f);
            v1.x = fmaxf(v1.x, 0.f); v1.y = fmaxf(v1.y, 0.f);
            v1.z = fmaxf(v1.z, 0.f); v1.w = fmaxf(v1.w, 0.f);
        }
        float* cp = C + (size_t)row * N + bn + colBase;
        *reinterpret_cast<float4*>(cp)     = v0;
        *reinterpret_cast<float4*>(cp + 4) = v1;
    }
}

// hidden = relu(features @ W1_top + protoW1[idx] )   (b1 folded into protoW1)
__global__ __launch_bounds__(256) void gemm1_kernel(const float* __restrict__ A,
                                                    const float* __restrict__ B) {
    sgemm_core<true>(A, B, g_hidden, g_protoW1);
}

// out = hidden @ W2 + b2
__global__ __launch_bounds__(256) void gemm2_kernel(const float* __restrict__ B,
                                                    const float* __restrict__ b2,
                                                    float* __restrict__ C) {
    sgemm_core<false>(g_hidden, B, C, b2);
}

// ---------------- launch ----------------
extern "C" void kernel_launch(void* const* d_in, const int* in_sizes, int n_in,
                              void* d_out, int out_size) {
    (void)in_sizes; (void)n_in; (void)out_size;
    const float* features = (const float*)d_in[0];
    const float* protos   = (const float*)d_in[1];
    const float* W1       = (const float*)d_in[2];
    const float* b1       = (const float*)d_in[3];
    const float* W2       = (const float*)d_in[4];
    const float* b2       = (const float*)d_in[5];
    float* out = (float*)d_out;

    argmin_kernel<<<BATCH / 8, 256>>>(features, protos);
    protow1_kernel<<<dim3(HDIM / 256, NFAM), 256>>>(protos, W1, b1);

    dim3 grid(HDIM / 128, BATCH / 128);   // (8, 256)
    gemm1_kernel<<<grid, 256>>>(features, W1);
    gemm2_kernel<<<grid, 256>>>(W2, b2, out);
}

// round 4
// speedup vs baseline: 2.0079x; 2.0079x over previous
#include <cuda_runtime.h>
#include <cuda_bf16.h>
#include <cstdint>

#define BATCH 32768
#define HDIM  1024
#define NFAM  10

// ---------------------------------------------------------------- scratch
__device__ __align__(16) int            g_nearest[BATCH];
__device__ __align__(16) float          g_protoW1[NFAM * HDIM];
__device__ __align__(16) __nv_bfloat16  g_feat_hi[(size_t)BATCH * HDIM];
__device__ __align__(16) __nv_bfloat16  g_feat_lo[(size_t)BATCH * HDIM];
__device__ __align__(16) __nv_bfloat16  g_hid_hi[(size_t)BATCH * HDIM];
__device__ __align__(16) __nv_bfloat16  g_hid_lo[(size_t)BATCH * HDIM];
__device__ __align__(16) __nv_bfloat16  g_w1t_hi[HDIM * HDIM];
__device__ __align__(16) __nv_bfloat16  g_w1t_lo[HDIM * HDIM];
__device__ __align__(16) __nv_bfloat16  g_w2t_hi[HDIM * HDIM];
__device__ __align__(16) __nv_bfloat16  g_w2t_lo[HDIM * HDIM];

// ---------------------------------------------------------------- helpers
__device__ __forceinline__ uint32_t smem_u32(const void* p) {
    uint32_t a;
    asm("{ .reg .u64 t; cvta.to.shared.u64 t, %1; cvt.u32.u64 %0, t; }" : "=r"(a) : "l"(p));
    return a;
}
__device__ __forceinline__ void cp16(uint32_t dst, const void* src) {
    asm volatile("cp.async.cg.shared.global [%0], [%1], 16;" :: "r"(dst), "l"(src) : "memory");
}
#define CP_COMMIT() asm volatile("cp.async.commit_group;" ::: "memory")
#define CP_WAIT1()  asm volatile("cp.async.wait_group 1;"  ::: "memory")

__device__ __forceinline__ void ldsm4(uint32_t& r0, uint32_t& r1, uint32_t& r2, uint32_t& r3,
                                      uint32_t addr) {
    asm volatile("ldmatrix.sync.aligned.m8n8.x4.shared.b16 {%0,%1,%2,%3}, [%4];"
                 : "=r"(r0), "=r"(r1), "=r"(r2), "=r"(r3) : "r"(addr));
}
__device__ __forceinline__ void mma16816(float* c, uint32_t a0, uint32_t a1, uint32_t a2,
                                         uint32_t a3, uint32_t b0, uint32_t b1) {
    asm volatile("mma.sync.aligned.m16n8k16.row.col.f32.bf16.bf16.f32 "
                 "{%0,%1,%2,%3}, {%4,%5,%6,%7}, {%8,%9}, {%0,%1,%2,%3};"
                 : "+f"(c[0]), "+f"(c[1]), "+f"(c[2]), "+f"(c[3])
                 : "r"(a0), "r"(a1), "r"(a2), "r"(a3), "r"(b0), "r"(b1));
}

__device__ __forceinline__ void split2(float v, __nv_bfloat16& h, __nv_bfloat16& l) {
    h = __float2bfloat16(v);
    l = __float2bfloat16(v - __bfloat162float(h));
}

// ---------------------------------------------------------------- prep kernels
__global__ __launch_bounds__(256) void split_feat_kernel(const float* __restrict__ in) {
    const size_t i = (size_t)blockIdx.x * 256 + threadIdx.x;   // float4 index
    float4 v = reinterpret_cast<const float4*>(in)[i];
    __nv_bfloat16 h0, h1, h2, h3, l0, l1, l2, l3;
    split2(v.x, h0, l0); split2(v.y, h1, l1); split2(v.z, h2, l2); split2(v.w, h3, l3);
    __nv_bfloat162* ph = reinterpret_cast<__nv_bfloat162*>(g_feat_hi) + i * 2;
    __nv_bfloat162* pl = reinterpret_cast<__nv_bfloat162*>(g_feat_lo) + i * 2;
    ph[0] = __nv_bfloat162(h0, h1); ph[1] = __nv_bfloat162(h2, h3);
    pl[0] = __nv_bfloat162(l0, l1); pl[1] = __nv_bfloat162(l2, l3);
}

// transpose + split: dst_hi[n*1024+k] = split(W[k*1024+n]).  WHICH: 0 -> w1t, 1 -> w2t.
template <int WHICH>
__global__ __launch_bounds__(256) void tsplit_kernel(const float* __restrict__ W) {
    __nv_bfloat16* thi = (WHICH == 0) ? g_w1t_hi : g_w2t_hi;
    __nv_bfloat16* tlo = (WHICH == 0) ? g_w1t_lo : g_w2t_lo;
    __shared__ float t[32][33];
    const int bx = blockIdx.x * 32, by = blockIdx.y * 32;
    const int tx = threadIdx.x, ty = threadIdx.y;   // (32, 8)
#pragma unroll
    for (int j = 0; j < 4; ++j)
        t[ty + 8 * j][tx] = W[(size_t)(by + ty + 8 * j) * HDIM + bx + tx];
    __syncthreads();
#pragma unroll
    for (int j = 0; j < 4; ++j) {
        float v = t[tx][ty + 8 * j];
        __nv_bfloat16 h, l; split2(v, h, l);
        thi[(size_t)(bx + ty + 8 * j) * HDIM + by + tx] = h;
        tlo[(size_t)(bx + ty + 8 * j) * HDIM + by + tx] = l;
    }
}

// argmin_j (p2 - 2 f.p) == argmin_j sum_h p*(p - 2f)
__global__ __launch_bounds__(256) void argmin_kernel(const float* __restrict__ feat,
                                                     const float* __restrict__ protos) {
    __shared__ float sp[NFAM * HDIM];
    for (int i = threadIdx.x; i < NFAM * HDIM; i += 256) sp[i] = protos[i];
    __syncthreads();

    const int warp = threadIdx.x >> 5;
    const int lane = threadIdx.x & 31;
    const int row  = blockIdx.x * 8 + warp;
    const float* f = feat + (size_t)row * HDIM;

    float acc[NFAM];
#pragma unroll
    for (int j = 0; j < NFAM; ++j) acc[j] = 0.f;
    for (int h = lane; h < HDIM; h += 32) {
        const float fv = f[h];
#pragma unroll
        for (int j = 0; j < NFAM; ++j) {
            const float p = sp[j * HDIM + h];
            acc[j] = fmaf(p, p - 2.f * fv, acc[j]);
        }
    }
#pragma unroll
    for (int j = 0; j < NFAM; ++j)
#pragma unroll
        for (int o = 16; o > 0; o >>= 1) acc[j] += __shfl_xor_sync(0xffffffffu, acc[j], o);
    if (lane == 0) {
        float best = acc[0]; int bi = 0;
#pragma unroll
        for (int j = 1; j < NFAM; ++j)
            if (acc[j] < best) { best = acc[j]; bi = j; }
        g_nearest[row] = bi;
    }
}

// protoW1[j][n] = b1[n] + protos[j] . W1[H + :, n]
__global__ __launch_bounds__(256) void protow1_kernel(const float* __restrict__ protos,
                                                      const float* __restrict__ W1,
                                                      const float* __restrict__ b1) {
    const int n = blockIdx.x * 256 + threadIdx.x;
    const int j = blockIdx.y;
    const float* p = protos + j * HDIM;
    const float* w = W1 + (size_t)HDIM * HDIM + n;
    float acc = b1[n];
#pragma unroll 8
    for (int h = 0; h < HDIM; ++h) acc = fmaf(p[h], w[(size_t)h * HDIM], acc);
    g_protoW1[j * HDIM + n] = acc;
}

// ---------------------------------------------------------------- HMMA GEMM
// C[128x128 tile] = sum over 3 segments of Aseg[.,1024] @ Bseg[.,1024]^T  (bf16 hi/lo split).
// Segments: (Ah,Bh), (Al,Bh), (Ah,Bl).  K_total = 3072, BK = 32 -> 96 slices.
// FUSE1 (GEMM1): A = g_feat, B = g_w1t; epilogue +protoW1[nearest], relu, split -> g_hid.
// !FUSE1 (GEMM2): A = g_hid,  B = g_w2t; epilogue +b2 -> fp32 out.
#define ROWB   80                      // padded row stride bytes (32 bf16 + 16B pad)
#define STAGEB (128 * ROWB)            // 10240 B per tile stage
#define NSTG   3
#define GSMEM  (2 * NSTG * STAGEB)     // 61440 B

template <bool FUSE1>
__global__ __launch_bounds__(256) void hmma_gemm_kernel(const float* __restrict__ b2,
                                                        float* __restrict__ out) {
    const __nv_bfloat16* __restrict__ Ahi = FUSE1 ? g_feat_hi : g_hid_hi;
    const __nv_bfloat16* __restrict__ Alo = FUSE1 ? g_feat_lo : g_hid_lo;
    const __nv_bfloat16* __restrict__ Bhi = FUSE1 ? g_w1t_hi : g_w2t_hi;
    const __nv_bfloat16* __restrict__ Blo = FUSE1 ? g_w1t_lo : g_w2t_lo;

    extern __shared__ char sm[];
    const uint32_t smA = smem_u32(sm);
    const uint32_t smB = smA + NSTG * STAGEB;

    const int tid  = threadIdx.x;
    const int lane = tid & 31;
    const int wid  = tid >> 5;
    const int wm   = (wid & 3) * 32;     // warp M offset
    const int wn   = (wid >> 2) * 64;    // warp N offset
    const int bm   = blockIdx.y * 128;
    const int bn   = blockIdx.x * 128;

    // loader mapping: each thread: 2 A-chunks + 2 B-chunks of 16B per stage
    const int c0   = tid;
    const int rA0  = c0 >> 2, kA0 = c0 & 3;
    const int rA1  = (c0 + 256) >> 2, kA1 = (c0 + 256) & 3;

    auto load_stage = [&](int s, int buf) {
        const int seg = s >> 5;
        const __nv_bfloat16* gA = (seg == 1) ? Alo : Ahi;
        const __nv_bfloat16* gB = (seg == 2) ? Blo : Bhi;
        const int ke = (s & 31) * 32;
        const uint32_t dA = smA + buf * STAGEB;
        const uint32_t dB = smB + buf * STAGEB;
        cp16(dA + rA0 * ROWB + kA0 * 16, gA + (size_t)(bm + rA0) * HDIM + ke + kA0 * 8);
        cp16(dA + rA1 * ROWB + kA1 * 16, gA + (size_t)(bm + rA1) * HDIM + ke + kA1 * 8);
        cp16(dB + rA0 * ROWB + kA0 * 16, gB + (size_t)(bn + rA0) * HDIM + ke + kA0 * 8);
        cp16(dB + rA1 * ROWB + kA1 * 16, gB + (size_t)(bn + rA1) * HDIM + ke + kA1 * 8);
    };

    float acc[2][8][4];
#pragma unroll
    for (int i = 0; i < 2; ++i)
#pragma unroll
        for (int j = 0; j < 8; ++j)
#pragma unroll
            for (int k = 0; k < 4; ++k) acc[i][j][k] = 0.f;

    // ldmatrix base addresses (per-stage offset added in loop)
    const uint32_t aAddr0 = smA + (wm + (lane & 15)) * ROWB + (lane >> 4) * 16;
    const uint32_t bAddr0 = smB + (wn + (lane & 7) + ((lane >> 4) << 3)) * ROWB
                                + (((lane >> 3) & 1) << 4);

    load_stage(0, 0); CP_COMMIT();
    load_stage(1, 1); CP_COMMIT();

    for (int s = 0; s < 96; ++s) {
        CP_WAIT1();
        __syncthreads();
        if (s + 2 < 96) load_stage(s + 2, (s + 2) % NSTG);
        CP_COMMIT();

        const int buf = s % NSTG;
        const uint32_t aB = aAddr0 + buf * STAGEB;
        const uint32_t bB = bAddr0 + buf * STAGEB;
#pragma unroll
        for (int ks = 0; ks < 2; ++ks) {
            const int ko = ks * 32;
            uint32_t a[2][4];
#pragma unroll
            for (int mt = 0; mt < 2; ++mt)
                ldsm4(a[mt][0], a[mt][1], a[mt][2], a[mt][3], aB + mt * 16 * ROWB + ko);
            uint32_t b[4][4];
#pragma unroll
            for (int g = 0; g < 4; ++g)
                ldsm4(b[g][0], b[g][1], b[g][2], b[g][3], bB + g * 16 * ROWB + ko);
#pragma unroll
            for (int mt = 0; mt < 2; ++mt)
#pragma unroll
                for (int g = 0; g < 4; ++g) {
                    mma16816(acc[mt][g * 2 + 0], a[mt][0], a[mt][1], a[mt][2], a[mt][3],
                             b[g][0], b[g][1]);
                    mma16816(acc[mt][g * 2 + 1], a[mt][0], a[mt][1], a[mt][2], a[mt][3],
                             b[g][2], b[g][3]);
                }
        }
    }

    // ---------------- epilogue ----------------
    const int grp = lane >> 2;      // row within m8
    const int tig = lane & 3;       // col pair
#pragma unroll
    for (int mt = 0; mt < 2; ++mt) {
        const int r0 = bm + wm + mt * 16 + grp;
        const int r1 = r0 + 8;
        const float* av0;
        const float* av1;
        if (FUSE1) {
            av0 = g_protoW1 + (size_t)g_nearest[r0] * HDIM;
            av1 = g_protoW1 + (size_t)g_nearest[r1] * HDIM;
        } else {
            av0 = b2; av1 = b2;
        }
#pragma unroll
        for (int gg = 0; gg < 8; ++gg) {
            const int col = bn + wn + (gg >> 1) * 16 + (gg & 1) * 8 + tig * 2;
            const float2 p0 = *reinterpret_cast<const float2*>(av0 + col);
            const float2 p1 = *reinterpret_cast<const float2*>(av1 + col);
            float v00 = acc[mt][gg][0] + p0.x, v01 = acc[mt][gg][1] + p0.y;
            float v10 = acc[mt][gg][2] + p1.x, v11 = acc[mt][gg][3] + p1.y;
            if (FUSE1) {
                v00 = fmaxf(v00, 0.f); v01 = fmaxf(v01, 0.f);
                v10 = fmaxf(v10, 0.f); v11 = fmaxf(v11, 0.f);
                __nv_bfloat16 h0, h1, h2, h3, l0, l1, l2, l3;
                split2(v00, h0, l0); split2(v01, h1, l1);
                split2(v10, h2, l2); split2(v11, h3, l3);
                *reinterpret_cast<__nv_bfloat162*>(g_hid_hi + (size_t)r0 * HDIM + col) = __nv_bfloat162(h0, h1);
                *reinterpret_cast<__nv_bfloat162*>(g_hid_lo + (size_t)r0 * HDIM + col) = __nv_bfloat162(l0, l1);
                *reinterpret_cast<__nv_bfloat162*>(g_hid_hi + (size_t)r1 * HDIM + col) = __nv_bfloat162(h2, h3);
                *reinterpret_cast<__nv_bfloat162*>(g_hid_lo + (size_t)r1 * HDIM + col) = __nv_bfloat162(l2, l3);
            } else {
                *reinterpret_cast<float2*>(out + (size_t)r0 * HDIM + col) = make_float2(v00, v01);
                *reinterpret_cast<float2*>(out + (size_t)r1 * HDIM + col) = make_float2(v10, v11);
            }
        }
    }
}

// ---------------------------------------------------------------- launch
extern "C" void kernel_launch(void* const* d_in, const int* in_sizes, int n_in,
                              void* d_out, int out_size) {
    (void)in_sizes; (void)n_in; (void)out_size;
    const float* features = (const float*)d_in[0];
    const float* protos   = (const float*)d_in[1];
    const float* W1       = (const float*)d_in[2];
    const float* b1       = (const float*)d_in[3];
    const float* W2       = (const float*)d_in[4];
    const float* b2       = (const float*)d_in[5];
    float* out = (float*)d_out;

    cudaFuncSetAttribute(hmma_gemm_kernel<true>,  cudaFuncAttributeMaxDynamicSharedMemorySize, GSMEM);
    cudaFuncSetAttribute(hmma_gemm_kernel<false>, cudaFuncAttributeMaxDynamicSharedMemorySize, GSMEM);

    split_feat_kernel<<<(BATCH * HDIM / 4) / 256, 256>>>(features);
    tsplit_kernel<0><<<dim3(32, 32), dim3(32, 8)>>>(W1);
    tsplit_kernel<1><<<dim3(32, 32), dim3(32, 8)>>>(W2);
    argmin_kernel<<<BATCH / 8, 256>>>(features, protos);
    protow1_kernel<<<dim3(HDIM / 256, NFAM), 256>>>(protos, W1, b1);

    dim3 grid(HDIM / 128, BATCH / 128);   // (8, 256)
    hmma_gemm_kernel<true><<<grid, 256, GSMEM>>>(nullptr, nullptr);
    hmma_gemm_kernel<false><<<grid, 256, GSMEM>>>(b2, out);
}